// round 15
// baseline (speedup 1.0000x reference)
#include <cuda_runtime.h>
#include <cuda_fp16.h>
#include <cstdint>

// Problem constants (fixed by the dataset)
#define MROWS 8192
#define NCOLS 8192
#define KROWS 8192
#define NNZ   256
#define BATCH 32

// 1024 CTAs x 8 warps = one warp per row, single wave. MUST be co-resident
// (enforced: launch_bounds(256,8) => regs<=32; smem 24KB/CTA => 8 CTAs/SM;
// 148 SMs x 8 = 1184 slots >= 1024).
#define CTAS 1024

// Intermediate bx = B @ x as fp16, [KROWS, BATCH] row-major (512 KB).
__device__ __half g_bx[KROWS * BATCH];
// Monotonic device-wide barrier ticket counter (replay-safe: phase = ticket/CTAS).
__device__ unsigned long long g_bar = 0ull;

// Gather geometry (proven best, R9/R12): warp = one row; g = lane>>3 (nnz
// subgroup 0..3), c = lane&7 (batch quad). One LDG fetches 4 distinct,
// fully-used rows (4 nnz) per instruction; metadata via LDS.64 broadcast.
__global__ void __launch_bounds__(256, 8)
fused_ell_kernel(const float* __restrict__ x,
                 const int*   __restrict__ a_idx,
                 const float* __restrict__ a_vals,
                 const int*   __restrict__ b_idx,
                 const float* __restrict__ b_vals,
                 float*       __restrict__ out,
                 __half*      __restrict__ bx)
{
    // s_bufA (16KB): stage-1 metadata [8][256] uint2.
    // After stage-1 (CTA-synced): bytes [0,8K) = stage-2 metadata half2
    // [8][128] uint2; bytes [8K,~9.2K) = s_out[32][9] for the store transpose.
    __shared__ __align__(16) unsigned char s_bufA[8 * NNZ * sizeof(uint2)];
    __shared__ __align__(16) uint2 s_m2a[8][NNZ / 2];   // stage-2 half1 (8KB)

    uint2 (*s_m1)[NNZ]      = reinterpret_cast<uint2(*)[NNZ]>(s_bufA);
    uint2 (*s_m2b)[NNZ / 2] = reinterpret_cast<uint2(*)[NNZ / 2]>(s_bufA);
    float (*s_out)[9]       = reinterpret_cast<float(*)[9]>(s_bufA + 8192);

    const int warp = threadIdx.x >> 5;
    const int lane = threadIdx.x & 31;
    const int g    = lane >> 3;
    const int c    = lane & 7;
    const int row  = blockIdx.x * 8 + warp;

    // ── Stage-1 metadata (B row) ──
    {
        const int4*   ip = reinterpret_cast<const int4*>(b_idx  + (size_t)row * NNZ);
        const float4* vp = reinterpret_cast<const float4*>(b_vals + (size_t)row * NNZ);
#pragma unroll
        for (int q = 0; q < 2; ++q) {
            const int4   iv = ip[q * 32 + lane];
            const float4 vv = vp[q * 32 + lane];
            const int base = (q * 32 + lane) * 4;
            s_m1[warp][base + 0] = make_uint2((unsigned)iv.x, __float_as_uint(vv.x));
            s_m1[warp][base + 1] = make_uint2((unsigned)iv.y, __float_as_uint(vv.y));
            s_m1[warp][base + 2] = make_uint2((unsigned)iv.z, __float_as_uint(vv.z));
            s_m1[warp][base + 3] = make_uint2((unsigned)iv.w, __float_as_uint(vv.w));
        }
    }
    __syncwarp();

    // ── Stage-1: bx[row] = fp16(B @ x), fp32 gathers (LDG.128, 4x128B lines) ──
    {
        const float4* src4 = reinterpret_cast<const float4*>(x) + c;
        float4 acc = make_float4(0.f, 0.f, 0.f, 0.f);
#pragma unroll 4
        for (int t = 0; t < NNZ / 4; ++t) {
            const uint2  p = s_m1[warp][t * 4 + g];
            const float4 d = __ldg(&src4[(size_t)p.x * (BATCH / 4)]);
            const float  v = __uint_as_float(p.y);
            acc.x = fmaf(v, d.x, acc.x);
            acc.y = fmaf(v, d.y, acc.y);
            acc.z = fmaf(v, d.z, acc.z);
            acc.w = fmaf(v, d.w, acc.w);
        }
#pragma unroll
        for (int off = 8; off < 32; off <<= 1) {
            acc.x += __shfl_xor_sync(0xffffffffu, acc.x, off);
            acc.y += __shfl_xor_sync(0xffffffffu, acc.y, off);
            acc.z += __shfl_xor_sync(0xffffffffu, acc.z, off);
            acc.w += __shfl_xor_sync(0xffffffffu, acc.w, off);
        }
        if (g == 0) {   // one contiguous 64B fp16 row per warp (lanes 0..7)
            const __half2 h0 = __floats2half2_rn(acc.x, acc.y);
            const __half2 h1 = __floats2half2_rn(acc.z, acc.w);
            uint2 s;
            s.x = *reinterpret_cast<const unsigned*>(&h0);
            s.y = *reinterpret_cast<const unsigned*>(&h1);
            reinterpret_cast<uint2*>(bx + (size_t)row * BATCH)[c] = s;
        }
    }
    __threadfence();   // publish bx before barrier arrival

    // ── Preload stage-2 metadata (A row) while other CTAs finish stage-1 ──
    const int4*   ip2 = reinterpret_cast<const int4*>(a_idx  + (size_t)row * NNZ);
    const float4* vp2 = reinterpret_cast<const float4*>(a_vals + (size_t)row * NNZ);
    {   // half1 (nnz 0..127) into dedicated region — safe immediately
        const int4   iv = ip2[lane];
        const float4 vv = vp2[lane];
        const int base = lane * 4;
        s_m2a[warp][base + 0] = make_uint2((unsigned)iv.x, __float_as_uint(vv.x));
        s_m2a[warp][base + 1] = make_uint2((unsigned)iv.y, __float_as_uint(vv.y));
        s_m2a[warp][base + 2] = make_uint2((unsigned)iv.z, __float_as_uint(vv.z));
        s_m2a[warp][base + 3] = make_uint2((unsigned)iv.w, __float_as_uint(vv.w));
    }
    __syncthreads();   // all warps done reading stage-1 metadata (s_bufA)
    {   // half2 (nnz 128..255) reuses s_bufA
        const int4   iv = ip2[32 + lane];
        const float4 vv = vp2[32 + lane];
        const int base = lane * 4;
        s_m2b[warp][base + 0] = make_uint2((unsigned)iv.x, __float_as_uint(vv.x));
        s_m2b[warp][base + 1] = make_uint2((unsigned)iv.y, __float_as_uint(vv.y));
        s_m2b[warp][base + 2] = make_uint2((unsigned)iv.z, __float_as_uint(vv.z));
        s_m2b[warp][base + 3] = make_uint2((unsigned)iv.w, __float_as_uint(vv.w));
    }
    __syncthreads();

    // ── Device-wide barrier: monotonic ticket, replay-safe ──
    if (threadIdx.x == 0) {
        const unsigned long long ticket = atomicAdd(&g_bar, 1ull);
        const unsigned long long target = (ticket / CTAS + 1ull) * (unsigned long long)CTAS;
        unsigned long long v;
        do {
            asm volatile("ld.acquire.gpu.u64 %0, [%1];"
                         : "=l"(v) : "l"(&g_bar) : "memory");
            if (v < target) __nanosleep(64);
        } while (v < target);
    }
    __syncthreads();

    // ── Stage-2: out[b][m] = A @ bx, fp16 gathers (LDG.64, 4x64B rows) ──
    {
        const uint2* src2 = reinterpret_cast<const uint2*>(bx) + c;
        float4 acc = make_float4(0.f, 0.f, 0.f, 0.f);
#pragma unroll 4
        for (int t = 0; t < NNZ / 8; ++t) {       // half1: nnz 0..127
            const uint2 p = s_m2a[warp][t * 4 + g];
            const uint2 d = __ldg(&src2[(size_t)p.x * (BATCH / 4)]);
            const float v = __uint_as_float(p.y);
            const float2 f0 = __half22float2(*reinterpret_cast<const __half2*>(&d.x));
            const float2 f1 = __half22float2(*reinterpret_cast<const __half2*>(&d.y));
            acc.x = fmaf(v, f0.x, acc.x);
            acc.y = fmaf(v, f0.y, acc.y);
            acc.z = fmaf(v, f1.x, acc.z);
            acc.w = fmaf(v, f1.y, acc.w);
        }
#pragma unroll 4
        for (int t = 0; t < NNZ / 8; ++t) {       // half2: nnz 128..255
            const uint2 p = s_m2b[warp][t * 4 + g];
            const uint2 d = __ldg(&src2[(size_t)p.x * (BATCH / 4)]);
            const float v = __uint_as_float(p.y);
            const float2 f0 = __half22float2(*reinterpret_cast<const __half2*>(&d.x));
            const float2 f1 = __half22float2(*reinterpret_cast<const __half2*>(&d.y));
            acc.x = fmaf(v, f0.x, acc.x);
            acc.y = fmaf(v, f0.y, acc.y);
            acc.z = fmaf(v, f1.x, acc.z);
            acc.w = fmaf(v, f1.y, acc.w);
        }
#pragma unroll
        for (int off = 8; off < 32; off <<= 1) {
            acc.x += __shfl_xor_sync(0xffffffffu, acc.x, off);
            acc.y += __shfl_xor_sync(0xffffffffu, acc.y, off);
            acc.z += __shfl_xor_sync(0xffffffffu, acc.z, off);
            acc.w += __shfl_xor_sync(0xffffffffu, acc.w, off);
        }
        if (g == 0) {   // lanes 0..7 hold batches 4c..4c+3 of this warp's row
            s_out[4 * c + 0][warp] = acc.x;
            s_out[4 * c + 1][warp] = acc.y;
            s_out[4 * c + 2][warp] = acc.z;
            s_out[4 * c + 3][warp] = acc.w;
        }
    }
    __syncthreads();

    // Transposed coalesced stores: thread t -> batch t/8, local row t%8.
    {
        const int b = threadIdx.x >> 3;
        const int j = threadIdx.x & 7;
        out[(size_t)b * MROWS + blockIdx.x * 8 + j] = s_out[b][j];
    }
}

extern "C" void kernel_launch(void* const* d_in, const int* in_sizes, int n_in,
                              void* d_out, int out_size)
{
    // metadata order:
    //   0: x      float32 [8192, 32]
    //   1: a_idx  int32   [8192, 256]
    //   2: a_vals float32 [8192, 256]
    //   3: b_idx  int32   [8192, 256]
    //   4: b_vals float32 [8192, 256]
    const float* x      = (const float*)d_in[0];
    const int*   a_idx  = (const int*)  d_in[1];
    const float* a_vals = (const float*)d_in[2];
    const int*   b_idx  = (const int*)  d_in[3];
    const float* b_vals = (const float*)d_in[4];
    float* out = (float*)d_out;  // (1, 32, 8192) fp32

    __half* bx;
    cudaGetSymbolAddress((void**)&bx, g_bx);

    fused_ell_kernel<<<CTAS, 256>>>(x, a_idx, a_vals, b_idx, b_vals, out, bx);
}

// round 16
// speedup vs baseline: 1.3462x; 1.3462x over previous
#include <cuda_runtime.h>
#include <cuda_fp16.h>
#include <cstdint>

// Problem constants (fixed by the dataset)
#define MROWS 8192
#define NCOLS 8192
#define KROWS 8192
#define NNZ   256
#define BATCH 32

// fp16 copies: x (converted each launch) and intermediate bx. 512 KB each.
__device__ __half g_xh[NCOLS * BATCH];
__device__ __half g_bx[KROWS * BATCH];

// ── Convert x to fp16. One float per thread, 262144 threads (1024 CTAs):
//    full-chip wave so the single L2 round-trip is latency-hidden, unlike the
//    R12 version (65K threads, 4.29us exposed-latency).
__global__ void __launch_bounds__(256)
x_to_half_kernel(const float* __restrict__ x, __half* __restrict__ xh)
{
    const int i = blockIdx.x * 256 + threadIdx.x;
    xh[i] = __float2half_rn(x[i]);
}

// Gather geometry (proven best): warp = one output row; g = lane>>3 (nnz
// subgroup 0..3), c = lane&7 (batch quad). One LDG.64 fetches 4 distinct,
// fully-used 64B fp16 rows (4 nnz); metadata via LDS.64 broadcast.

// ── Stage 1: bx = fp16(B @ xh). fp16 gathers, fp32 accumulate, 64B row store.
__global__ void __launch_bounds__(256)
ell_stage1_kernel(const int*    __restrict__ idx,
                  const float*  __restrict__ vals,
                  const __half* __restrict__ src,
                  __half*       __restrict__ dst)
{
    __shared__ __align__(16) uint2 s_pair[8][NNZ];

    const int warp = threadIdx.x >> 5;
    const int lane = threadIdx.x & 31;
    const int g    = lane >> 3;
    const int c    = lane & 7;
    const int row  = blockIdx.x * 8 + warp;

    {
        const int4*   ip = reinterpret_cast<const int4*>(idx  + (size_t)row * NNZ);
        const float4* vp = reinterpret_cast<const float4*>(vals + (size_t)row * NNZ);
#pragma unroll
        for (int q = 0; q < NNZ / (32 * 4); ++q) {
            const int4   iv = ip[q * 32 + lane];
            const float4 vv = vp[q * 32 + lane];
            const int base = (q * 32 + lane) * 4;
            s_pair[warp][base + 0] = make_uint2((unsigned)iv.x, __float_as_uint(vv.x));
            s_pair[warp][base + 1] = make_uint2((unsigned)iv.y, __float_as_uint(vv.y));
            s_pair[warp][base + 2] = make_uint2((unsigned)iv.z, __float_as_uint(vv.z));
            s_pair[warp][base + 3] = make_uint2((unsigned)iv.w, __float_as_uint(vv.w));
        }
    }
    __syncwarp();

    const uint2* src2 = reinterpret_cast<const uint2*>(src) + c;  // lane's 8B slice
    float4 acc = make_float4(0.f, 0.f, 0.f, 0.f);

#pragma unroll 4
    for (int t = 0; t < NNZ / 4; ++t) {
        const uint2 p = s_pair[warp][t * 4 + g];                  // LDS.64 metadata
        const uint2 d = __ldg(&src2[(size_t)p.x * (BATCH / 4)]);  // 4x64B rows/instr
        const float v = __uint_as_float(p.y);
        const float2 f0 = __half22float2(*reinterpret_cast<const __half2*>(&d.x));
        const float2 f1 = __half22float2(*reinterpret_cast<const __half2*>(&d.y));
        acc.x = fmaf(v, f0.x, acc.x);
        acc.y = fmaf(v, f0.y, acc.y);
        acc.z = fmaf(v, f1.x, acc.z);
        acc.w = fmaf(v, f1.y, acc.w);
    }

#pragma unroll
    for (int off = 8; off < 32; off <<= 1) {
        acc.x += __shfl_xor_sync(0xffffffffu, acc.x, off);
        acc.y += __shfl_xor_sync(0xffffffffu, acc.y, off);
        acc.z += __shfl_xor_sync(0xffffffffu, acc.z, off);
        acc.w += __shfl_xor_sync(0xffffffffu, acc.w, off);
    }

    if (g == 0) {  // one contiguous 64B fp16 row per warp (lanes 0..7)
        const __half2 h0 = __floats2half2_rn(acc.x, acc.y);
        const __half2 h1 = __floats2half2_rn(acc.z, acc.w);
        uint2 s;
        s.x = *reinterpret_cast<const unsigned*>(&h0);
        s.y = *reinterpret_cast<const unsigned*>(&h1);
        reinterpret_cast<uint2*>(dst + (size_t)row * BATCH)[c] = s;
    }
}

// ── Stage 2: out[b][m] = A @ bx. fp16 gathers, fp32 accumulate; smem
//    transpose so the CTA writes 32 coalesced 32B segments.
__global__ void __launch_bounds__(256)
ell_stage2_kernel(const int*    __restrict__ idx,
                  const float*  __restrict__ vals,
                  const __half* __restrict__ src,
                  float*        __restrict__ dst)
{
    __shared__ __align__(16) uint2 s_pair[8][NNZ];
    __shared__ float s_out[BATCH][9];   // [b][warp], padded stride 9

    const int warp = threadIdx.x >> 5;
    const int lane = threadIdx.x & 31;
    const int g    = lane >> 3;
    const int c    = lane & 7;
    const int row  = blockIdx.x * 8 + warp;

    {
        const int4*   ip = reinterpret_cast<const int4*>(idx  + (size_t)row * NNZ);
        const float4* vp = reinterpret_cast<const float4*>(vals + (size_t)row * NNZ);
#pragma unroll
        for (int q = 0; q < NNZ / (32 * 4); ++q) {
            const int4   iv = ip[q * 32 + lane];
            const float4 vv = vp[q * 32 + lane];
            const int base = (q * 32 + lane) * 4;
            s_pair[warp][base + 0] = make_uint2((unsigned)iv.x, __float_as_uint(vv.x));
            s_pair[warp][base + 1] = make_uint2((unsigned)iv.y, __float_as_uint(vv.y));
            s_pair[warp][base + 2] = make_uint2((unsigned)iv.z, __float_as_uint(vv.z));
            s_pair[warp][base + 3] = make_uint2((unsigned)iv.w, __float_as_uint(vv.w));
        }
    }
    __syncwarp();

    const uint2* src2 = reinterpret_cast<const uint2*>(src) + c;
    float4 acc = make_float4(0.f, 0.f, 0.f, 0.f);

#pragma unroll 4
    for (int t = 0; t < NNZ / 4; ++t) {
        const uint2 p = s_pair[warp][t * 4 + g];
        const uint2 d = __ldg(&src2[(size_t)p.x * (BATCH / 4)]);
        const float v = __uint_as_float(p.y);
        const float2 f0 = __half22float2(*reinterpret_cast<const __half2*>(&d.x));
        const float2 f1 = __half22float2(*reinterpret_cast<const __half2*>(&d.y));
        acc.x = fmaf(v, f0.x, acc.x);
        acc.y = fmaf(v, f0.y, acc.y);
        acc.z = fmaf(v, f1.x, acc.z);
        acc.w = fmaf(v, f1.y, acc.w);
    }

#pragma unroll
    for (int off = 8; off < 32; off <<= 1) {
        acc.x += __shfl_xor_sync(0xffffffffu, acc.x, off);
        acc.y += __shfl_xor_sync(0xffffffffu, acc.y, off);
        acc.z += __shfl_xor_sync(0xffffffffu, acc.z, off);
        acc.w += __shfl_xor_sync(0xffffffffu, acc.w, off);
    }

    if (g == 0) {   // lanes 0..7 hold batches 4c..4c+3 of this warp's row
        s_out[4 * c + 0][warp] = acc.x;
        s_out[4 * c + 1][warp] = acc.y;
        s_out[4 * c + 2][warp] = acc.z;
        s_out[4 * c + 3][warp] = acc.w;
    }
    __syncthreads();

    // Thread t -> batch t/8, local row t%8: 32 coalesced 32B segment stores.
    {
        const int b = threadIdx.x >> 3;
        const int j = threadIdx.x & 7;
        dst[(size_t)b * MROWS + blockIdx.x * 8 + j] = s_out[b][j];
    }
}

extern "C" void kernel_launch(void* const* d_in, const int* in_sizes, int n_in,
                              void* d_out, int out_size)
{
    // metadata order:
    //   0: x      float32 [8192, 32]
    //   1: a_idx  int32   [8192, 256]
    //   2: a_vals float32 [8192, 256]
    //   3: b_idx  int32   [8192, 256]
    //   4: b_vals float32 [8192, 256]
    const float* x      = (const float*)d_in[0];
    const int*   a_idx  = (const int*)  d_in[1];
    const float* a_vals = (const float*)d_in[2];
    const int*   b_idx  = (const int*)  d_in[3];
    const float* b_vals = (const float*)d_in[4];
    float* out = (float*)d_out;  // (1, 32, 8192) fp32

    __half *xh, *bx;
    cudaGetSymbolAddress((void**)&xh, g_xh);
    cudaGetSymbolAddress((void**)&bx, g_bx);

    // Pre-pass: xh = fp16(x) — full-chip wave, latency-hidden.
    x_to_half_kernel<<<(NCOLS * BATCH) / 256, 256>>>(x, xh);
    // Stage 1: bx = fp16(B @ xh)   (fp16 gathers)
    ell_stage1_kernel<<<KROWS / 8, 256>>>(b_idx, b_vals, xh, bx);
    // Stage 2: out = (A @ bx)^T    (fp16 gathers, transposed coalesced stores)
    ell_stage2_kernel<<<MROWS / 8, 256>>>(a_idx, a_vals, bx, out);
}